// round 4
// baseline (speedup 1.0000x reference)
#include <cuda_runtime.h>
#include <math.h>

#define N_IMG 2
#define CCH   256
#define HH    256
#define WW    256
#define PHB   7
#define PWB   7
#define NBINS (PHB * PWB)
#define NPHASE (NBINS * 2)
#define NROIS 1024
#define SCALE 0.25f

// 128 MB static scratch for NHWC-transposed features
__device__ float g_nhwc[(size_t)N_IMG * HH * WW * CCH];

// ---------------------------------------------------------------------------
// Kernel 1: NCHW -> NHWC transpose, fully vectorized (LDG.128/STG.128 both
// sides). Tile = 32 channels x 128 hw, register 4x4 transpose + XOR-swizzled
// smem (conflict-free), coalesced float4 flush.
// ---------------------------------------------------------------------------
__global__ void __launch_bounds__(256) nchw_to_nhwc_kernel(const float* __restrict__ in)
{
    __shared__ float4 tile[128 * 8];
    const int n   = blockIdx.z;
    const int hw0 = blockIdx.x * 128;
    const int c0  = blockIdx.y * 32;
    const int t   = threadIdx.x;

    const float* src = in     + (size_t)n * CCH * HH * WW;
    float*       dst = g_nhwc + (size_t)n * HH * WW * CCH;

    const int hw4 = t & 31;
    const int c4w = t >> 5;

    float vv[4][4];
#pragma unroll
    for (int j = 0; j < 4; ++j) {
        float4 ld = *(const float4*)(src + (size_t)(c0 + c4w * 4 + j) * (HH * WW)
                                         + hw0 + hw4 * 4);
        vv[j][0] = ld.x; vv[j][1] = ld.y; vv[j][2] = ld.z; vv[j][3] = ld.w;
    }
#pragma unroll
    for (int r = 0; r < 4; ++r) {
        float4 o = make_float4(vv[0][r], vv[1][r], vv[2][r], vv[3][r]);
        const int hw = hw4 * 4 + r;
        tile[hw * 8 + (c4w ^ ((hw >> 2) & 7))] = o;
    }
    __syncthreads();
#pragma unroll
    for (int k = 0; k < 4; ++k) {
        const int idx = t + k * 256;
        const int hw  = idx >> 3;
        const int c4  = idx & 7;
        float4 f = tile[hw * 8 + (c4 ^ ((hw >> 2) & 7))];
        *(float4*)(dst + (size_t)(hw0 + hw) * CCH + c0 + c4 * 4) = f;
    }
}

// ---------------------------------------------------------------------------
// Kernel 2: rotated RoIAlign gather on NHWC features.
// Block = 1 roi, 512 threads. Stage A: 98 threads precompute, per (bin,phase),
// the 8 gather indices + 8 pre-scaled bilinear weights into smem (uniform math
// done ONCE instead of by all 64 channel groups). Stage B: main loop is pure
// broadcast-LDS + LDG.128 + FMA, staged into smem for a fully coalesced
// float4 output flush. 4 blocks/SM for ~100% theoretical occupancy.
// ---------------------------------------------------------------------------
__global__ void __launch_bounds__(512, 4) roialign_rot_kernel(
    const float* __restrict__ rois, float* __restrict__ out)
{
    __shared__ float s_out[CCH * NBINS];       // 50176 B
    __shared__ int   s_idx[NPHASE * 8];        // 3136 B
    __shared__ float s_w  [NPHASE * 8];        // 3136 B

    const int roi    = blockIdx.x;
    const int tid    = threadIdx.x;
    const int cgrp   = tid & 63;       // float4 channel group
    const int bslice = tid >> 6;       // 0..7

    const float* r = rois + roi * 6;
    const int b = (int)r[0];

    // ---- Stage A: per-(bin,phase) precompute by 98 threads ----
    if (tid < NPHASE) {
        const int bin = tid >> 1;
        const int sp  = tid & 1;
        const int ph  = bin / PWB;
        const int pw  = bin - ph * PWB;

        const float cx = fmaf(r[1], SCALE, -0.5f);
        const float cy = fmaf(r[2], SCALE, -0.5f);
        const float rw = r[3] * SCALE;
        const float rh = r[4] * SCALE;
        float sn, cs;
        sincosf(r[5], &sn, &cs);

        const float bin_h = rh * (1.0f / PHB);
        const float bin_w = rw * (1.0f / PWB);
        const float yy = -0.5f * rh + ((float)ph + ((float)sp + 0.5f) * 0.5f) * bin_h;

#pragma unroll
        for (int ix = 0; ix < 2; ++ix) {
            const float xx = -0.5f * rw + ((float)pw + ((float)ix + 0.5f) * 0.5f) * bin_w;
            float y = yy * cs - xx * sn + cy;
            float x = yy * sn + xx * cs + cx;

            const bool valid = (y > -1.0f) & (y < (float)HH) &
                               (x > -1.0f) & (x < (float)WW);
            y = fmaxf(y, 0.0f);
            x = fmaxf(x, 0.0f);

            int yl = (int)y;
            int xl = (int)x;
            int yh, xh; float ly, lx;
            if (yl >= HH - 1) { yl = HH - 1; yh = HH - 1; ly = 0.f; }
            else              { yh = yl + 1; ly = y - (float)yl; }
            if (xl >= WW - 1) { xl = WW - 1; xh = WW - 1; lx = 0.f; }
            else              { xh = xl + 1; lx = x - (float)xl; }

            const float vsc = valid ? 0.25f : 0.0f;   // folds the /4 mean
            const float hy = 1.f - ly, hx = 1.f - lx;
            const int base = tid * 8 + ix * 4;
            s_w[base + 0] = hy * hx * vsc;
            s_w[base + 1] = hy * lx * vsc;
            s_w[base + 2] = ly * hx * vsc;
            s_w[base + 3] = ly * lx * vsc;

            const int rl = yl * WW, rh2 = yh * WW;
            s_idx[base + 0] = (rl  + xl) << 6;   // * (CCH/4)
            s_idx[base + 1] = (rl  + xh) << 6;
            s_idx[base + 2] = (rh2 + xl) << 6;
            s_idx[base + 3] = (rh2 + xh) << 6;
        }
    }
    __syncthreads();

    const float4* __restrict__ feat =
        (const float4*)g_nhwc + (size_t)b * (HH * WW * (CCH / 4)) + cgrp;

    // ---- Stage B: gather loop (broadcast LDS + LDG.128 + FMA only) ----
    for (int bin = bslice; bin < NBINS; bin += 8) {
        float a0 = 0.f, a1 = 0.f, a2 = 0.f, a3 = 0.f;

#pragma unroll
        for (int sp = 0; sp < 2; ++sp) {
            const int base = (bin * 2 + sp) * 8;
            float4 v[8];
            float  w[8];
#pragma unroll
            for (int i = 0; i < 8; ++i) {
                w[i] = s_w[base + i];
                v[i] = __ldg(feat + s_idx[base + i]);
            }
#pragma unroll
            for (int i = 0; i < 8; ++i) {
                a0 = fmaf(w[i], v[i].x, a0);
                a1 = fmaf(w[i], v[i].y, a1);
                a2 = fmaf(w[i], v[i].z, a2);
                a3 = fmaf(w[i], v[i].w, a3);
            }
        }

        const int cb = cgrp * 4;
        s_out[(cb + 0) * NBINS + bin] = a0;
        s_out[(cb + 1) * NBINS + bin] = a1;
        s_out[(cb + 2) * NBINS + bin] = a2;
        s_out[(cb + 3) * NBINS + bin] = a3;
    }

    __syncthreads();
    float4* o4 = (float4*)(out + (size_t)roi * (CCH * NBINS));
    const float4* s4 = (const float4*)s_out;
#pragma unroll 4
    for (int i = tid; i < (CCH * NBINS) / 4; i += 512) {
        o4[i] = s4[i];
    }
}

extern "C" void kernel_launch(void* const* d_in, const int* in_sizes, int n_in,
                              void* d_out, int out_size)
{
    const float* feat = (const float*)d_in[0];
    const float* rois = (const float*)d_in[1];
    if (in_sizes[0] == NROIS * 6) {
        rois = (const float*)d_in[0];
        feat = (const float*)d_in[1];
    }
    float* out = (float*)d_out;

    dim3 tg((HH * WW) / 128, CCH / 32, N_IMG);
    nchw_to_nhwc_kernel<<<tg, 256>>>(feat);

    roialign_rot_kernel<<<NROIS, 512>>>(rois, out);
}

// round 5
// speedup vs baseline: 1.2605x; 1.2605x over previous
#include <cuda_runtime.h>
#include <math.h>

#define N_IMG 2
#define CCH   256
#define HH    256
#define WW    256
#define PHB   7
#define PWB   7
#define NBINS (PHB * PWB)
#define NPHASE (NBINS * 2)
#define NROIS 1024
#define SCALE 0.25f

// 128 MB static scratch for NHWC-transposed features
__device__ float g_nhwc[(size_t)N_IMG * HH * WW * CCH];

// ---------------------------------------------------------------------------
// Kernel 1: NCHW -> NHWC transpose, fully vectorized (LDG.128/STG.128 both
// sides). Tile = 32 channels x 128 hw, register 4x4 transpose + XOR-swizzled
// smem (conflict-free), coalesced float4 flush.
// ---------------------------------------------------------------------------
__global__ void __launch_bounds__(256) nchw_to_nhwc_kernel(const float* __restrict__ in)
{
    __shared__ float4 tile[128 * 8];
    const int n   = blockIdx.z;
    const int hw0 = blockIdx.x * 128;
    const int c0  = blockIdx.y * 32;
    const int t   = threadIdx.x;

    const float* src = in     + (size_t)n * CCH * HH * WW;
    float*       dst = g_nhwc + (size_t)n * HH * WW * CCH;

    const int hw4 = t & 31;
    const int c4w = t >> 5;

    float vv[4][4];
#pragma unroll
    for (int j = 0; j < 4; ++j) {
        float4 ld = *(const float4*)(src + (size_t)(c0 + c4w * 4 + j) * (HH * WW)
                                         + hw0 + hw4 * 4);
        vv[j][0] = ld.x; vv[j][1] = ld.y; vv[j][2] = ld.z; vv[j][3] = ld.w;
    }
#pragma unroll
    for (int r = 0; r < 4; ++r) {
        float4 o = make_float4(vv[0][r], vv[1][r], vv[2][r], vv[3][r]);
        const int hw = hw4 * 4 + r;
        tile[hw * 8 + (c4w ^ ((hw >> 2) & 7))] = o;
    }
    __syncthreads();
#pragma unroll
    for (int k = 0; k < 4; ++k) {
        const int idx = t + k * 256;
        const int hw  = idx >> 3;
        const int c4  = idx & 7;
        float4 f = tile[hw * 8 + (c4 ^ ((hw >> 2) & 7))];
        *(float4*)(dst + (size_t)(hw0 + hw) * CCH + c0 + c4 * 4) = f;
    }
}

// ---------------------------------------------------------------------------
// Kernel 2: rotated RoIAlign gather on NHWC features.
// Block = 1 roi, 512 threads. Stage A: 98 threads precompute per-(bin,phase)
// gather indices + pre-scaled weights into smem (uniform math once per roi).
// Stage B: pure broadcast-LDS + LDG.128 + FMA, structured as rolling batches
// of 4 in-flight float4 loads (fits the 3-blocks/SM register budget while
// preserving memory-level parallelism — R4 showed a 4-block reg cap
// serializes the loads and is 1.5x slower). smem staging -> coalesced
// float4 output flush.
// ---------------------------------------------------------------------------
__global__ void __launch_bounds__(512, 3) roialign_rot_kernel(
    const float* __restrict__ rois, float* __restrict__ out)
{
    __shared__ float s_out[CCH * NBINS];       // 50176 B
    __shared__ int   s_idx[NPHASE * 8];        // 3136 B
    __shared__ float s_w  [NPHASE * 8];        // 3136 B

    const int roi    = blockIdx.x;
    const int tid    = threadIdx.x;
    const int cgrp   = tid & 63;       // float4 channel group
    const int bslice = tid >> 6;       // 0..7

    const float* r = rois + roi * 6;
    const int b = (int)r[0];

    // ---- Stage A: per-(bin,phase) precompute by 98 threads ----
    if (tid < NPHASE) {
        const int bin = tid >> 1;
        const int sp  = tid & 1;
        const int ph  = bin / PWB;
        const int pw  = bin - ph * PWB;

        const float cx = fmaf(r[1], SCALE, -0.5f);
        const float cy = fmaf(r[2], SCALE, -0.5f);
        const float rw = r[3] * SCALE;
        const float rh = r[4] * SCALE;
        float sn, cs;
        sincosf(r[5], &sn, &cs);

        const float bin_h = rh * (1.0f / PHB);
        const float bin_w = rw * (1.0f / PWB);
        const float yy = -0.5f * rh + ((float)ph + ((float)sp + 0.5f) * 0.5f) * bin_h;

#pragma unroll
        for (int ix = 0; ix < 2; ++ix) {
            const float xx = -0.5f * rw + ((float)pw + ((float)ix + 0.5f) * 0.5f) * bin_w;
            float y = yy * cs - xx * sn + cy;
            float x = yy * sn + xx * cs + cx;

            const bool valid = (y > -1.0f) & (y < (float)HH) &
                               (x > -1.0f) & (x < (float)WW);
            y = fmaxf(y, 0.0f);
            x = fmaxf(x, 0.0f);

            int yl = (int)y;
            int xl = (int)x;
            int yh, xh; float ly, lx;
            if (yl >= HH - 1) { yl = HH - 1; yh = HH - 1; ly = 0.f; }
            else              { yh = yl + 1; ly = y - (float)yl; }
            if (xl >= WW - 1) { xl = WW - 1; xh = WW - 1; lx = 0.f; }
            else              { xh = xl + 1; lx = x - (float)xl; }

            const float vsc = valid ? 0.25f : 0.0f;   // folds the /4 mean
            const float hy = 1.f - ly, hx = 1.f - lx;
            const int base = tid * 8 + ix * 4;
            s_w[base + 0] = hy * hx * vsc;
            s_w[base + 1] = hy * lx * vsc;
            s_w[base + 2] = ly * hx * vsc;
            s_w[base + 3] = ly * lx * vsc;

            const int rl = yl * WW, rh2 = yh * WW;
            s_idx[base + 0] = (rl  + xl) << 6;   // * (CCH/4)
            s_idx[base + 1] = (rl  + xh) << 6;
            s_idx[base + 2] = (rh2 + xl) << 6;
            s_idx[base + 3] = (rh2 + xh) << 6;
        }
    }
    __syncthreads();

    const float4* __restrict__ feat =
        (const float4*)g_nhwc + (size_t)b * (HH * WW * (CCH / 4)) + cgrp;

    // ---- Stage B: gather loop. Rolling batches of 4 in-flight LDG.128. ----
    for (int bin = bslice; bin < NBINS; bin += 8) {
        float a0 = 0.f, a1 = 0.f, a2 = 0.f, a3 = 0.f;
        const int base = bin * 16;   // 2 phases x 8 entries

        // Prologue: launch batch 0 (entries 0..3).
        float4 va[4]; float wa[4];
#pragma unroll
        for (int i = 0; i < 4; ++i) {
            wa[i] = s_w[base + i];
            va[i] = __ldg(feat + s_idx[base + i]);
        }

#pragma unroll
        for (int g = 1; g < 4; ++g) {
            // Launch next batch while previous is consumed.
            float4 vb[4]; float wb[4];
#pragma unroll
            for (int i = 0; i < 4; ++i) {
                wb[i] = s_w[base + g * 4 + i];
                vb[i] = __ldg(feat + s_idx[base + g * 4 + i]);
            }
#pragma unroll
            for (int i = 0; i < 4; ++i) {
                a0 = fmaf(wa[i], va[i].x, a0);
                a1 = fmaf(wa[i], va[i].y, a1);
                a2 = fmaf(wa[i], va[i].z, a2);
                a3 = fmaf(wa[i], va[i].w, a3);
            }
#pragma unroll
            for (int i = 0; i < 4; ++i) { va[i] = vb[i]; wa[i] = wb[i]; }
        }
        // Epilogue: consume last batch.
#pragma unroll
        for (int i = 0; i < 4; ++i) {
            a0 = fmaf(wa[i], va[i].x, a0);
            a1 = fmaf(wa[i], va[i].y, a1);
            a2 = fmaf(wa[i], va[i].z, a2);
            a3 = fmaf(wa[i], va[i].w, a3);
        }

        const int cb = cgrp * 4;
        s_out[(cb + 0) * NBINS + bin] = a0;
        s_out[(cb + 1) * NBINS + bin] = a1;
        s_out[(cb + 2) * NBINS + bin] = a2;
        s_out[(cb + 3) * NBINS + bin] = a3;
    }

    __syncthreads();
    float4* o4 = (float4*)(out + (size_t)roi * (CCH * NBINS));
    const float4* s4 = (const float4*)s_out;
#pragma unroll 4
    for (int i = tid; i < (CCH * NBINS) / 4; i += 512) {
        o4[i] = s4[i];
    }
}

extern "C" void kernel_launch(void* const* d_in, const int* in_sizes, int n_in,
                              void* d_out, int out_size)
{
    const float* feat = (const float*)d_in[0];
    const float* rois = (const float*)d_in[1];
    if (in_sizes[0] == NROIS * 6) {
        rois = (const float*)d_in[0];
        feat = (const float*)d_in[1];
    }
    float* out = (float*)d_out;

    dim3 tg((HH * WW) / 128, CCH / 32, N_IMG);
    nchw_to_nhwc_kernel<<<tg, 256>>>(feat);

    roialign_rot_kernel<<<NROIS, 512>>>(rois, out);
}

// round 6
// speedup vs baseline: 1.6101x; 1.2774x over previous
#include <cuda_runtime.h>
#include <cuda_fp16.h>
#include <math.h>

#define N_IMG 2
#define CCH   256
#define HH    256
#define WW    256
#define PHB   7
#define PWB   7
#define NBINS (PHB * PWB)
#define NPHASE (NBINS * 2)
#define NROIS 1024
#define SCALE 0.25f

// 64 MB static scratch: NHWC features in fp16 (fits entirely in the 126 MB L2).
// Stored as uint4 (8 halves) for guaranteed 16B alignment.
__device__ uint4 g_nhwc_h[(size_t)N_IMG * HH * WW * CCH / 8];

// ---------------------------------------------------------------------------
// Kernel 1: NCHW fp32 -> NHWC fp16 transpose.
// Tile = 32 channels x 128 hw. Register 4x4 transpose through XOR-swizzled
// fp32 smem; the flush converts pairs of float4 -> 8 halves (uint4) and
// stores 16B-coalesced. Traffic: 256 MB read + 64 MB write.
// ---------------------------------------------------------------------------
__global__ void __launch_bounds__(256) nchw_to_nhwc_h_kernel(const float* __restrict__ in)
{
    __shared__ float4 tile[128 * 8];
    const int n   = blockIdx.z;
    const int hw0 = blockIdx.x * 128;
    const int c0  = blockIdx.y * 32;
    const int t   = threadIdx.x;

    const float* src = in + (size_t)n * CCH * HH * WW;
    __half*      dst = (__half*)g_nhwc_h + (size_t)n * HH * WW * CCH;

    const int hw4 = t & 31;    // float4 column along hw (0..31)
    const int c4w = t >> 5;    // 4-channel group (0..7)

    float vv[4][4];
#pragma unroll
    for (int j = 0; j < 4; ++j) {
        float4 ld = *(const float4*)(src + (size_t)(c0 + c4w * 4 + j) * (HH * WW)
                                         + hw0 + hw4 * 4);
        vv[j][0] = ld.x; vv[j][1] = ld.y; vv[j][2] = ld.z; vv[j][3] = ld.w;
    }
#pragma unroll
    for (int r = 0; r < 4; ++r) {
        float4 o = make_float4(vv[0][r], vv[1][r], vv[2][r], vv[3][r]);
        const int hw = hw4 * 4 + r;
        tile[hw * 8 + (c4w ^ ((hw >> 2) & 7))] = o;
    }
    __syncthreads();

    // Flush: 512 uint4 outputs (128 hw x 4 groups of 8 channels), 2 per thread.
#pragma unroll
    for (int k = 0; k < 2; ++k) {
        const int idx = t + k * 256;       // 0..511
        const int cq  = idx & 3;           // 8-channel group
        const int hw  = idx >> 2;
        const int sw  = (hw >> 2) & 7;
        float4 f0 = tile[hw * 8 + ((2 * cq)     ^ sw)];
        float4 f1 = tile[hw * 8 + ((2 * cq + 1) ^ sw)];
        __half2 h[4];
        h[0] = __floats2half2_rn(f0.x, f0.y);
        h[1] = __floats2half2_rn(f0.z, f0.w);
        h[2] = __floats2half2_rn(f1.x, f1.y);
        h[3] = __floats2half2_rn(f1.z, f1.w);
        *(uint4*)(dst + (size_t)(hw0 + hw) * CCH + c0 + cq * 8) = *(uint4*)h;
    }
}

// ---------------------------------------------------------------------------
// Kernel 2: rotated RoIAlign gather on fp16 NHWC features (L2-resident).
// Block = 1 roi, 512 threads = 32 channel-groups (8 halves / 16B) x 16
// bin-slices. Stage A: 98 threads precompute per-(bin,phase) indices +
// pre-scaled weights (uniform math once). Stage B: batches of 8 in-flight
// 16B loads, half->float convert, fp32 FMA accumulate. smem staging ->
// coalesced float4 output flush.
// ---------------------------------------------------------------------------
__global__ void __launch_bounds__(512, 2) roialign_rot_kernel(
    const float* __restrict__ rois, float* __restrict__ out)
{
    __shared__ float s_out[CCH * NBINS];       // 50176 B
    __shared__ int   s_idx[NPHASE * 8];        // 3136 B
    __shared__ float s_w  [NPHASE * 8];        // 3136 B

    const int roi    = blockIdx.x;
    const int tid    = threadIdx.x;
    const int cgrp   = tid & 31;       // 8-channel group (16B)
    const int bslice = tid >> 5;       // 0..15

    const float* r = rois + roi * 6;
    const int b = (int)r[0];

    // ---- Stage A: per-(bin,phase) precompute by 98 threads ----
    if (tid < NPHASE) {
        const int bin = tid >> 1;
        const int sp  = tid & 1;
        const int ph  = bin / PWB;
        const int pw  = bin - ph * PWB;

        const float cx = fmaf(r[1], SCALE, -0.5f);
        const float cy = fmaf(r[2], SCALE, -0.5f);
        const float rw = r[3] * SCALE;
        const float rh = r[4] * SCALE;
        float sn, cs;
        sincosf(r[5], &sn, &cs);

        const float bin_h = rh * (1.0f / PHB);
        const float bin_w = rw * (1.0f / PWB);
        const float yy = -0.5f * rh + ((float)ph + ((float)sp + 0.5f) * 0.5f) * bin_h;

#pragma unroll
        for (int ix = 0; ix < 2; ++ix) {
            const float xx = -0.5f * rw + ((float)pw + ((float)ix + 0.5f) * 0.5f) * bin_w;
            float y = yy * cs - xx * sn + cy;
            float x = yy * sn + xx * cs + cx;

            const bool valid = (y > -1.0f) & (y < (float)HH) &
                               (x > -1.0f) & (x < (float)WW);
            y = fmaxf(y, 0.0f);
            x = fmaxf(x, 0.0f);

            int yl = (int)y;
            int xl = (int)x;
            int yh, xh; float ly, lx;
            if (yl >= HH - 1) { yl = HH - 1; yh = HH - 1; ly = 0.f; }
            else              { yh = yl + 1; ly = y - (float)yl; }
            if (xl >= WW - 1) { xl = WW - 1; xh = WW - 1; lx = 0.f; }
            else              { xh = xl + 1; lx = x - (float)xl; }

            const float vsc = valid ? 0.25f : 0.0f;   // folds the /4 mean
            const float hy = 1.f - ly, hx = 1.f - lx;
            const int base = tid * 8 + ix * 4;
            s_w[base + 0] = hy * hx * vsc;
            s_w[base + 1] = hy * lx * vsc;
            s_w[base + 2] = ly * hx * vsc;
            s_w[base + 3] = ly * lx * vsc;

            const int rl = yl * WW, rh2 = yh * WW;
            s_idx[base + 0] = (rl  + xl) << 5;   // * (CCH/8)
            s_idx[base + 1] = (rl  + xh) << 5;
            s_idx[base + 2] = (rh2 + xl) << 5;
            s_idx[base + 3] = (rh2 + xh) << 5;
        }
    }
    __syncthreads();

    const uint4* __restrict__ feat =
        g_nhwc_h + (size_t)b * (HH * WW * (CCH / 8)) + cgrp;

    // ---- Stage B: gather loop, 8 x 16B loads in flight per phase ----
    for (int bin = bslice; bin < NBINS; bin += 16) {
        float a0 = 0.f, a1 = 0.f, a2 = 0.f, a3 = 0.f;
        float a4 = 0.f, a5 = 0.f, a6 = 0.f, a7 = 0.f;

#pragma unroll
        for (int sp = 0; sp < 2; ++sp) {
            const int base = (bin * 2 + sp) * 8;
            uint4 v[8];
            float w[8];
#pragma unroll
            for (int i = 0; i < 8; ++i) {
                w[i] = s_w[base + i];
                v[i] = __ldg(feat + s_idx[base + i]);
            }
#pragma unroll
            for (int i = 0; i < 8; ++i) {
                const __half2* hp = (const __half2*)&v[i];
                float2 f0 = __half22float2(hp[0]);
                float2 f1 = __half22float2(hp[1]);
                float2 f2 = __half22float2(hp[2]);
                float2 f3 = __half22float2(hp[3]);
                a0 = fmaf(w[i], f0.x, a0);
                a1 = fmaf(w[i], f0.y, a1);
                a2 = fmaf(w[i], f1.x, a2);
                a3 = fmaf(w[i], f1.y, a3);
                a4 = fmaf(w[i], f2.x, a4);
                a5 = fmaf(w[i], f2.y, a5);
                a6 = fmaf(w[i], f3.x, a6);
                a7 = fmaf(w[i], f3.y, a7);
            }
        }

        const int cb = cgrp * 8;
        s_out[(cb + 0) * NBINS + bin] = a0;
        s_out[(cb + 1) * NBINS + bin] = a1;
        s_out[(cb + 2) * NBINS + bin] = a2;
        s_out[(cb + 3) * NBINS + bin] = a3;
        s_out[(cb + 4) * NBINS + bin] = a4;
        s_out[(cb + 5) * NBINS + bin] = a5;
        s_out[(cb + 6) * NBINS + bin] = a6;
        s_out[(cb + 7) * NBINS + bin] = a7;
    }

    __syncthreads();
    float4* o4 = (float4*)(out + (size_t)roi * (CCH * NBINS));
    const float4* s4 = (const float4*)s_out;
#pragma unroll 4
    for (int i = tid; i < (CCH * NBINS) / 4; i += 512) {
        o4[i] = s4[i];
    }
}

extern "C" void kernel_launch(void* const* d_in, const int* in_sizes, int n_in,
                              void* d_out, int out_size)
{
    const float* feat = (const float*)d_in[0];
    const float* rois = (const float*)d_in[1];
    if (in_sizes[0] == NROIS * 6) {
        rois = (const float*)d_in[0];
        feat = (const float*)d_in[1];
    }
    float* out = (float*)d_out;

    dim3 tg((HH * WW) / 128, CCH / 32, N_IMG);
    nchw_to_nhwc_h_kernel<<<tg, 256>>>(feat);

    roialign_rot_kernel<<<NROIS, 512>>>(rois, out);
}

// round 7
// speedup vs baseline: 2.0443x; 1.2696x over previous
#include <cuda_runtime.h>
#include <cuda_fp16.h>
#include <math.h>

#define N_IMG 2
#define CCH   256
#define HH    256
#define WW    256
#define PHB   7
#define PWB   7
#define NBINS (PHB * PWB)
#define NPHASE (NBINS * 2)
#define NROIS 1024
#define SCALE 0.25f
#define CBLK  128                 // channels per gather block

// 64 MB static scratch: NHWC features in fp16 (fully L2-resident).
__device__ uint4 g_nhwc_h[(size_t)N_IMG * HH * WW * CCH / 8];

// ---------------------------------------------------------------------------
// Kernel 1: NCHW fp32 -> NHWC fp16 transpose (unchanged from R6; ~30 us,
// near the DRAM floor for 256 MB read + 64 MB write).
// ---------------------------------------------------------------------------
__global__ void __launch_bounds__(256) nchw_to_nhwc_h_kernel(const float* __restrict__ in)
{
    __shared__ float4 tile[128 * 8];
    const int n   = blockIdx.z;
    const int hw0 = blockIdx.x * 128;
    const int c0  = blockIdx.y * 32;
    const int t   = threadIdx.x;

    const float* src = in + (size_t)n * CCH * HH * WW;
    __half*      dst = (__half*)g_nhwc_h + (size_t)n * HH * WW * CCH;

    const int hw4 = t & 31;
    const int c4w = t >> 5;

    float vv[4][4];
#pragma unroll
    for (int j = 0; j < 4; ++j) {
        float4 ld = *(const float4*)(src + (size_t)(c0 + c4w * 4 + j) * (HH * WW)
                                         + hw0 + hw4 * 4);
        vv[j][0] = ld.x; vv[j][1] = ld.y; vv[j][2] = ld.z; vv[j][3] = ld.w;
    }
#pragma unroll
    for (int r = 0; r < 4; ++r) {
        float4 o = make_float4(vv[0][r], vv[1][r], vv[2][r], vv[3][r]);
        const int hw = hw4 * 4 + r;
        tile[hw * 8 + (c4w ^ ((hw >> 2) & 7))] = o;
    }
    __syncthreads();

#pragma unroll
    for (int k = 0; k < 2; ++k) {
        const int idx = t + k * 256;       // 0..511
        const int cq  = idx & 3;           // 8-channel group
        const int hw  = idx >> 2;
        const int sw  = (hw >> 2) & 7;
        float4 f0 = tile[hw * 8 + ((2 * cq)     ^ sw)];
        float4 f1 = tile[hw * 8 + ((2 * cq + 1) ^ sw)];
        __half2 h[4];
        h[0] = __floats2half2_rn(f0.x, f0.y);
        h[1] = __floats2half2_rn(f0.z, f0.w);
        h[2] = __floats2half2_rn(f1.x, f1.y);
        h[3] = __floats2half2_rn(f1.z, f1.w);
        *(uint4*)(dst + (size_t)(hw0 + hw) * CCH + c0 + cq * 8) = *(uint4*)h;
    }
}

// ---------------------------------------------------------------------------
// Kernel 2: rotated RoIAlign gather on fp16 NHWC features (L2-resident).
// Block = (roi, channel-half): 128 channels, 256 threads = 32 uint2-groups
// (4 halves / 8B) x 8 bin-slices. Stage A: 98 threads precompute per-
// (bin,phase) indices + pre-scaled weights. Stage B: 8-deep in-flight 8B
// load batches, half->float, fp32 FMA. ~46 regs -> 5 blocks/SM (62.5% occ)
// while keeping MLP=8. smem staging (25 KB) -> coalesced float4 flush.
// ---------------------------------------------------------------------------
__global__ void __launch_bounds__(256, 5) roialign_rot_kernel(
    const float* __restrict__ rois, float* __restrict__ out)
{
    __shared__ float s_out[CBLK * NBINS];      // 25088 B
    __shared__ int   s_idx[NPHASE * 8];        // 3136 B
    __shared__ float s_w  [NPHASE * 8];        // 3136 B

    const int roi    = blockIdx.x;
    const int c0     = blockIdx.y * CBLK;      // 0 or 128
    const int tid    = threadIdx.x;
    const int cgrp   = tid & 31;               // uint2 channel group (4 halves)
    const int bslice = tid >> 5;               // 0..7

    const float* r = rois + roi * 6;
    const int b = (int)r[0];

    // ---- Stage A: per-(bin,phase) precompute by 98 threads ----
    if (tid < NPHASE) {
        const int bin = tid >> 1;
        const int sp  = tid & 1;
        const int ph  = bin / PWB;
        const int pw  = bin - ph * PWB;

        const float cx = fmaf(r[1], SCALE, -0.5f);
        const float cy = fmaf(r[2], SCALE, -0.5f);
        const float rw = r[3] * SCALE;
        const float rh = r[4] * SCALE;
        float sn, cs;
        sincosf(r[5], &sn, &cs);

        const float bin_h = rh * (1.0f / PHB);
        const float bin_w = rw * (1.0f / PWB);
        const float yy = -0.5f * rh + ((float)ph + ((float)sp + 0.5f) * 0.5f) * bin_h;

#pragma unroll
        for (int ix = 0; ix < 2; ++ix) {
            const float xx = -0.5f * rw + ((float)pw + ((float)ix + 0.5f) * 0.5f) * bin_w;
            float y = yy * cs - xx * sn + cy;
            float x = yy * sn + xx * cs + cx;

            const bool valid = (y > -1.0f) & (y < (float)HH) &
                               (x > -1.0f) & (x < (float)WW);
            y = fmaxf(y, 0.0f);
            x = fmaxf(x, 0.0f);

            int yl = (int)y;
            int xl = (int)x;
            int yh, xh; float ly, lx;
            if (yl >= HH - 1) { yl = HH - 1; yh = HH - 1; ly = 0.f; }
            else              { yh = yl + 1; ly = y - (float)yl; }
            if (xl >= WW - 1) { xl = WW - 1; xh = WW - 1; lx = 0.f; }
            else              { xh = xl + 1; lx = x - (float)xl; }

            const float vsc = valid ? 0.25f : 0.0f;   // folds the /4 mean
            const float hy = 1.f - ly, hx = 1.f - lx;
            const int base = tid * 8 + ix * 4;
            s_w[base + 0] = hy * hx * vsc;
            s_w[base + 1] = hy * lx * vsc;
            s_w[base + 2] = ly * hx * vsc;
            s_w[base + 3] = ly * lx * vsc;

            const int rl = yl * WW, rh2 = yh * WW;
            s_idx[base + 0] = (rl  + xl) << 6;   // * (CCH/4) uint2 units
            s_idx[base + 1] = (rl  + xh) << 6;
            s_idx[base + 2] = (rh2 + xl) << 6;
            s_idx[base + 3] = (rh2 + xh) << 6;
        }
    }
    __syncthreads();

    const uint2* __restrict__ feat =
        (const uint2*)g_nhwc_h + (size_t)b * (HH * WW * (CCH / 4))
        + (c0 / 4) + cgrp;

    // ---- Stage B: gather loop, 8 x 8B loads in flight per phase ----
    for (int bin = bslice; bin < NBINS; bin += 8) {
        float a0 = 0.f, a1 = 0.f, a2 = 0.f, a3 = 0.f;

#pragma unroll
        for (int sp = 0; sp < 2; ++sp) {
            const int base = (bin * 2 + sp) * 8;
            const int4   i01 = *(const int4*)&s_idx[base];
            const int4   i23 = *(const int4*)&s_idx[base + 4];
            const float4 w01 = *(const float4*)&s_w[base];
            const float4 w23 = *(const float4*)&s_w[base + 4];

            uint2 v[8];
            v[0] = __ldg(feat + i01.x);
            v[1] = __ldg(feat + i01.y);
            v[2] = __ldg(feat + i01.z);
            v[3] = __ldg(feat + i01.w);
            v[4] = __ldg(feat + i23.x);
            v[5] = __ldg(feat + i23.y);
            v[6] = __ldg(feat + i23.z);
            v[7] = __ldg(feat + i23.w);

            const float w[8] = {w01.x, w01.y, w01.z, w01.w,
                                w23.x, w23.y, w23.z, w23.w};
#pragma unroll
            for (int i = 0; i < 8; ++i) {
                const __half2* hp = (const __half2*)&v[i];
                float2 f0 = __half22float2(hp[0]);
                float2 f1 = __half22float2(hp[1]);
                a0 = fmaf(w[i], f0.x, a0);
                a1 = fmaf(w[i], f0.y, a1);
                a2 = fmaf(w[i], f1.x, a2);
                a3 = fmaf(w[i], f1.y, a3);
            }
        }

        const int cb = cgrp * 4;
        s_out[(cb + 0) * NBINS + bin] = a0;
        s_out[(cb + 1) * NBINS + bin] = a1;
        s_out[(cb + 2) * NBINS + bin] = a2;
        s_out[(cb + 3) * NBINS + bin] = a3;
    }

    __syncthreads();
    // Block's 128 channels are contiguous in the output: coalesced flush.
    float4* o4 = (float4*)(out + (size_t)roi * (CCH * NBINS) + (size_t)c0 * NBINS);
    const float4* s4 = (const float4*)s_out;
    for (int i = tid; i < (CBLK * NBINS) / 4; i += 256) {
        o4[i] = s4[i];
    }
}

extern "C" void kernel_launch(void* const* d_in, const int* in_sizes, int n_in,
                              void* d_out, int out_size)
{
    const float* feat = (const float*)d_in[0];
    const float* rois = (const float*)d_in[1];
    if (in_sizes[0] == NROIS * 6) {
        rois = (const float*)d_in[0];
        feat = (const float*)d_in[1];
    }
    float* out = (float*)d_out;

    dim3 tg((HH * WW) / 128, CCH / 32, N_IMG);
    nchw_to_nhwc_h_kernel<<<tg, 256>>>(feat);

    dim3 gg(NROIS, CCH / CBLK, 1);
    roialign_rot_kernel<<<gg, 256>>>(rois, out);
}